// round 1
// baseline (speedup 1.0000x reference)
#include <cuda_runtime.h>
#include <cstdint>

// Problem constants (fixed by the dataset)
#define NNODES 20000
#define NEDGES 256000
#define HD     128
#define NR     100
#define NB     64
#define NQ     2048   // B query pairs

// ---------------- scratch (no allocation allowed) ----------------
__device__ float g_out1[NNODES * HD];        // layer1 pre-activation
__device__ float g_out2[NNODES * 2 * HD];    // layer2 output
__device__ float g_z[NNODES * HD];           // latent
__device__ float g_hr[NQ * HD];              // head*rel

// ---------------- vectorized global reduction -------------------
__device__ __forceinline__ void red_add_v4(float* p, float a, float b, float c, float d) {
    asm volatile("red.global.v4.f32.add [%0], {%1,%2,%3,%4};"
                 :: "l"(p), "f"(a), "f"(b), "f"(c), "f"(d) : "memory");
}

// ================= self-loop layer 1: out1 = X@lw1 + b1 =========
// X[n] = embed[h[n]]; block = 128 threads, 8 nodes per block
__global__ void selfloop1_kernel(const float* __restrict__ embed,
                                 const int* __restrict__ h,
                                 const float* __restrict__ lw1,
                                 const float* __restrict__ b1) {
    __shared__ float xs[8][HD];
    int t = threadIdx.x;
    int n0 = blockIdx.x * 8;
#pragma unroll
    for (int nb = 0; nb < 8; nb++) {
        int node = n0 + nb;
        xs[nb][t] = embed[(size_t)h[node] * HD + t];
    }
    __syncthreads();
    float acc[8] = {0,0,0,0,0,0,0,0};
#pragma unroll 4
    for (int k = 0; k < HD; k++) {
        float w = lw1[k * HD + t];
#pragma unroll
        for (int nb = 0; nb < 8; nb++) acc[nb] = fmaf(xs[nb][k], w, acc[nb]);
    }
    float bias = b1[t];
#pragma unroll
    for (int nb = 0; nb < 8; nb++)
        g_out1[(size_t)(n0 + nb) * HD + t] = acc[nb] + bias;
}

// ================= edge messages layer 1 (atomic scatter) =======
// one warp per edge; lane l handles blocks 2l,2l+1 (features 4l..4l+3)
__global__ void edge1_kernel(const float* __restrict__ embed,
                             const int* __restrict__ h,
                             const int* __restrict__ src,
                             const int* __restrict__ dst,
                             const int* __restrict__ et,
                             const float* __restrict__ norm,
                             const float* __restrict__ W1) {
    int e = blockIdx.x * 8 + (threadIdx.x >> 5);
    if (e >= NEDGES) return;
    int l = threadIdx.x & 31;
    int s = src[e], d = dst[e], r = et[e];
    float nr = norm[e];
    const float* xrow = embed + (size_t)h[s] * HD;
    float4 xv = *(const float4*)(xrow + 4 * l);
    const float* w = W1 + (size_t)r * 256 + l * 8;   // [64][2][2] per rel
    float4 w0 = *(const float4*)(w);      // block 2l:   w00 w01 w10 w11
    float4 w1 = *(const float4*)(w + 4);  // block 2l+1
    float m0 = (xv.x * w0.x + xv.y * w0.z) * nr;
    float m1 = (xv.x * w0.y + xv.y * w0.w) * nr;
    float m2 = (xv.z * w1.x + xv.w * w1.z) * nr;
    float m3 = (xv.z * w1.y + xv.w * w1.w) * nr;
    red_add_v4(g_out1 + (size_t)d * HD + 4 * l, m0, m1, m2, m3);
}

// ================= self-loop layer 2: out2 = relu(out1)@lw2 + b2
// block = 256 threads, 4 nodes per block
__global__ void selfloop2_kernel(const float* __restrict__ lw2,
                                 const float* __restrict__ b2) {
    __shared__ float xs[4][HD];
    int t = threadIdx.x;
    int n0 = blockIdx.x * 4;
    for (int idx = t; idx < 4 * HD; idx += 256) {
        int nb = idx >> 7, k = idx & 127;
        float v = g_out1[(size_t)(n0 + nb) * HD + k];
        xs[nb][k] = v > 0.f ? v : 0.f;
    }
    __syncthreads();
    float acc[4] = {0,0,0,0};
#pragma unroll 4
    for (int k = 0; k < HD; k++) {
        float w = lw2[k * 256 + t];
#pragma unroll
        for (int nb = 0; nb < 4; nb++) acc[nb] = fmaf(xs[nb][k], w, acc[nb]);
    }
    float bias = b2[t];
#pragma unroll
    for (int nb = 0; nb < 4; nb++)
        g_out2[(size_t)(n0 + nb) * 256 + t] = acc[nb] + bias;
}

// ================= edge messages layer 2 ========================
// lane l: blocks 2l,2l+1 -> outputs 8l..8l+7
__global__ void edge2_kernel(const int* __restrict__ src,
                             const int* __restrict__ dst,
                             const int* __restrict__ et,
                             const float* __restrict__ norm,
                             const float* __restrict__ W2) {
    int e = blockIdx.x * 8 + (threadIdx.x >> 5);
    if (e >= NEDGES) return;
    int l = threadIdx.x & 31;
    int s = src[e], d = dst[e], r = et[e];
    float nr = norm[e];
    const float* xrow = g_out1 + (size_t)s * HD;
    float4 xv = *(const float4*)(xrow + 4 * l);
    xv.x = xv.x > 0.f ? xv.x : 0.f;
    xv.y = xv.y > 0.f ? xv.y : 0.f;
    xv.z = xv.z > 0.f ? xv.z : 0.f;
    xv.w = xv.w > 0.f ? xv.w : 0.f;
    const float* w = W2 + (size_t)r * 512 + l * 16;  // [64][2][4] per rel
    float4 wa0 = *(const float4*)(w);       // block 2l, i=0
    float4 wa1 = *(const float4*)(w + 4);   // block 2l, i=1
    float4 wb0 = *(const float4*)(w + 8);   // block 2l+1, i=0
    float4 wb1 = *(const float4*)(w + 12);  // block 2l+1, i=1
    float m0 = (xv.x * wa0.x + xv.y * wa1.x) * nr;
    float m1 = (xv.x * wa0.y + xv.y * wa1.y) * nr;
    float m2 = (xv.x * wa0.z + xv.y * wa1.z) * nr;
    float m3 = (xv.x * wa0.w + xv.y * wa1.w) * nr;
    float m4 = (xv.z * wb0.x + xv.w * wb1.x) * nr;
    float m5 = (xv.z * wb0.y + xv.w * wb1.y) * nr;
    float m6 = (xv.z * wb0.z + xv.w * wb1.z) * nr;
    float m7 = (xv.z * wb0.w + xv.w * wb1.w) * nr;
    float* p = g_out2 + (size_t)d * 256 + 8 * l;
    red_add_v4(p,     m0, m1, m2, m3);
    red_add_v4(p + 4, m4, m5, m6, m7);
}

// ================= z = m + sqrt(softplus(hv)+1e-8)*eps ==========
__global__ void z_kernel(const float* __restrict__ eps) {
    int i = blockIdx.x * blockDim.x + threadIdx.x;   // over N*HD
    if (i >= NNODES * HD) return;
    int n = i >> 7, j = i & 127;
    float m  = g_out2[(size_t)n * 256 + j];
    float hv = g_out2[(size_t)n * 256 + 128 + j];
    // stable softplus = max(x,0) + log1p(exp(-|x|))
    float sp = fmaxf(hv, 0.f) + log1pf(expf(-fabsf(hv)));
    float v = sp + 1e-8f;
    g_z[i] = fmaf(sqrtf(v), eps[i], m);
}

// ================= hr = z[head] * w_rel[rel] ====================
__global__ void hr_kernel(const int* __restrict__ head_ids,
                          const int* __restrict__ rel_ids,
                          const float* __restrict__ w_rel) {
    int i = blockIdx.x * blockDim.x + threadIdx.x;   // over NQ*HD
    if (i >= NQ * HD) return;
    int b = i >> 7, j = i & 127;
    g_hr[i] = g_z[(size_t)head_ids[b] * HD + j] * w_rel[(size_t)rel_ids[b] * HD + j];
}

// ================= scores = hr @ z^T  [2048 x 20000] ============
// 64x64 tile per block, 256 threads, 4x4 per thread, BK=64 (2 chunks)
__global__ void scores_kernel(float* __restrict__ C) {
    __shared__ float As[64][68];
    __shared__ float Bs[64][68];
    int tid = threadIdx.x;
    int tx = tid & 15, ty = tid >> 4;
    int m0 = blockIdx.y * 64, n0 = blockIdx.x * 64;
    float acc[4][4] = {};
#pragma unroll
    for (int kk = 0; kk < HD; kk += 64) {
#pragma unroll
        for (int i = 0; i < 4; i++) {
            int idx = tid + i * 256;        // 0..1023
            int row = idx >> 4;             // 0..63
            int c4  = idx & 15;
            float4 va = *(const float4*)(g_hr + (size_t)(m0 + row) * HD + kk + c4 * 4);
            As[c4 * 4 + 0][row] = va.x;
            As[c4 * 4 + 1][row] = va.y;
            As[c4 * 4 + 2][row] = va.z;
            As[c4 * 4 + 3][row] = va.w;
            int gn = n0 + row;
            float4 vb = make_float4(0.f, 0.f, 0.f, 0.f);
            if (gn < NNODES)
                vb = *(const float4*)(g_z + (size_t)gn * HD + kk + c4 * 4);
            Bs[c4 * 4 + 0][row] = vb.x;
            Bs[c4 * 4 + 1][row] = vb.y;
            Bs[c4 * 4 + 2][row] = vb.z;
            Bs[c4 * 4 + 3][row] = vb.w;
        }
        __syncthreads();
#pragma unroll 8
        for (int k = 0; k < 64; k++) {
            float4 a = *(float4*)(&As[k][ty * 4]);
            float4 b = *(float4*)(&Bs[k][tx * 4]);
            acc[0][0] = fmaf(a.x, b.x, acc[0][0]);
            acc[0][1] = fmaf(a.x, b.y, acc[0][1]);
            acc[0][2] = fmaf(a.x, b.z, acc[0][2]);
            acc[0][3] = fmaf(a.x, b.w, acc[0][3]);
            acc[1][0] = fmaf(a.y, b.x, acc[1][0]);
            acc[1][1] = fmaf(a.y, b.y, acc[1][1]);
            acc[1][2] = fmaf(a.y, b.z, acc[1][2]);
            acc[1][3] = fmaf(a.y, b.w, acc[1][3]);
            acc[2][0] = fmaf(a.z, b.x, acc[2][0]);
            acc[2][1] = fmaf(a.z, b.y, acc[2][1]);
            acc[2][2] = fmaf(a.z, b.z, acc[2][2]);
            acc[2][3] = fmaf(a.z, b.w, acc[2][3]);
            acc[3][0] = fmaf(a.w, b.x, acc[3][0]);
            acc[3][1] = fmaf(a.w, b.y, acc[3][1]);
            acc[3][2] = fmaf(a.w, b.z, acc[3][2]);
            acc[3][3] = fmaf(a.w, b.w, acc[3][3]);
        }
        __syncthreads();
    }
#pragma unroll
    for (int i = 0; i < 4; i++) {
        int gm = m0 + ty * 4 + i;
        int gn = n0 + tx * 4;
        if (gn < NNODES)
            *(float4*)(C + (size_t)gm * NNODES + gn) =
                make_float4(acc[i][0], acc[i][1], acc[i][2], acc[i][3]);
    }
}

// =================================================================
extern "C" void kernel_launch(void* const* d_in, const int* in_sizes, int n_in,
                              void* d_out, int out_size) {
    const int*   h        = (const int*)d_in[0];
    const int*   src      = (const int*)d_in[1];
    const int*   dst      = (const int*)d_in[2];
    const int*   etypes   = (const int*)d_in[3];
    const float* norm     = (const float*)d_in[4];
    const int*   head_ids = (const int*)d_in[5];
    const int*   rel_ids  = (const int*)d_in[6];
    const float* embed    = (const float*)d_in[7];
    const float* W1       = (const float*)d_in[8];
    const float* lw1      = (const float*)d_in[9];
    const float* b1       = (const float*)d_in[10];
    const float* W2       = (const float*)d_in[11];
    const float* lw2      = (const float*)d_in[12];
    const float* b2       = (const float*)d_in[13];
    const float* w_rel    = (const float*)d_in[14];
    const float* eps      = (const float*)d_in[15];
    float* out = (float*)d_out;

    // layer 1: self-loop GEMM writes out1, edges scatter-add into it
    selfloop1_kernel<<<NNODES / 8, 128>>>(embed, h, lw1, b1);
    edge1_kernel<<<NEDGES / 8, 256>>>(embed, h, src, dst, etypes, norm, W1);

    // layer 2 (relu applied on read of out1)
    selfloop2_kernel<<<NNODES / 4, 256>>>(lw2, b2);
    edge2_kernel<<<NEDGES / 8, 256>>>(src, dst, etypes, norm, W2);

    // reparameterized latent
    z_kernel<<<(NNODES * HD + 255) / 256, 256>>>(eps);

    // DistMult decoder
    hr_kernel<<<(NQ * HD + 255) / 256, 256>>>(head_ids, rel_ids, w_rel);
    dim3 grid((NNODES + 63) / 64, NQ / 64);
    scores_kernel<<<grid, 256>>>(out);
}

// round 6
// speedup vs baseline: 1.1790x; 1.1790x over previous
#include <cuda_runtime.h>
#include <cstdint>

// Problem constants (fixed by the dataset)
#define NNODES 20000
#define NEDGES 256000
#define HD     128
#define NR     100
#define NB     64
#define NQ     2048   // B query pairs

// ---------------- scratch (no allocation allowed) ----------------
__device__ float g_out1[NNODES * HD];        // layer1 pre-activation
__device__ float g_out2[NNODES * 2 * HD];    // layer2 output
__device__ float g_z[NNODES * HD];           // latent
__device__ float g_hr[NQ * HD];              // head*rel

// ---------------- vectorized global reduction -------------------
__device__ __forceinline__ void red_add_v4(float* p, float a, float b, float c, float d) {
    asm volatile("red.global.v4.f32.add [%0], {%1,%2,%3,%4};"
                 :: "l"(p), "f"(a), "f"(b), "f"(c), "f"(d) : "memory");
}

// ---------------- packed f32x2 helpers (Blackwell) ---------------
__device__ __forceinline__ unsigned long long pack2(float x, float y) {
    unsigned long long r;
    asm("mov.b64 %0, {%1, %2};" : "=l"(r) : "f"(x), "f"(y));
    return r;
}
__device__ __forceinline__ void ffma2(unsigned long long& c,
                                      unsigned long long a,
                                      unsigned long long b) {
    asm("fma.rn.f32x2 %0, %1, %2, %0;" : "+l"(c) : "l"(a), "l"(b));
}
__device__ __forceinline__ float2 unpack2(unsigned long long v) {
    float2 r;
    asm("mov.b64 {%0, %1}, %2;" : "=f"(r.x), "=f"(r.y) : "l"(v));
    return r;
}

// ================= self-loop layer 1: out1 = X@lw1 + b1 =========
__global__ void selfloop1_kernel(const float* __restrict__ embed,
                                 const int* __restrict__ h,
                                 const float* __restrict__ lw1,
                                 const float* __restrict__ b1) {
    __shared__ float xs[8][HD];
    int t = threadIdx.x;
    int n0 = blockIdx.x * 8;
#pragma unroll
    for (int nb = 0; nb < 8; nb++) {
        int node = n0 + nb;
        xs[nb][t] = embed[(size_t)h[node] * HD + t];
    }
    __syncthreads();
    float acc[8] = {0,0,0,0,0,0,0,0};
#pragma unroll 4
    for (int k = 0; k < HD; k++) {
        float w = lw1[k * HD + t];
#pragma unroll
        for (int nb = 0; nb < 8; nb++) acc[nb] = fmaf(xs[nb][k], w, acc[nb]);
    }
    float bias = b1[t];
#pragma unroll
    for (int nb = 0; nb < 8; nb++)
        g_out1[(size_t)(n0 + nb) * HD + t] = acc[nb] + bias;
}

// ================= edge messages layer 1 (atomic scatter) =======
__global__ void edge1_kernel(const float* __restrict__ embed,
                             const int* __restrict__ h,
                             const int* __restrict__ src,
                             const int* __restrict__ dst,
                             const int* __restrict__ et,
                             const float* __restrict__ norm,
                             const float* __restrict__ W1) {
    int e = blockIdx.x * 8 + (threadIdx.x >> 5);
    if (e >= NEDGES) return;
    int l = threadIdx.x & 31;
    int s = src[e], d = dst[e], r = et[e];
    float nr = norm[e];
    const float* xrow = embed + (size_t)h[s] * HD;
    float4 xv = *(const float4*)(xrow + 4 * l);
    const float* w = W1 + (size_t)r * 256 + l * 8;   // [64][2][2] per rel
    float4 w0 = *(const float4*)(w);      // block 2l
    float4 w1 = *(const float4*)(w + 4);  // block 2l+1
    float m0 = (xv.x * w0.x + xv.y * w0.z) * nr;
    float m1 = (xv.x * w0.y + xv.y * w0.w) * nr;
    float m2 = (xv.z * w1.x + xv.w * w1.z) * nr;
    float m3 = (xv.z * w1.y + xv.w * w1.w) * nr;
    red_add_v4(g_out1 + (size_t)d * HD + 4 * l, m0, m1, m2, m3);
}

// ================= self-loop layer 2: out2 = relu(out1)@lw2 + b2
__global__ void selfloop2_kernel(const float* __restrict__ lw2,
                                 const float* __restrict__ b2) {
    __shared__ float xs[4][HD];
    int t = threadIdx.x;
    int n0 = blockIdx.x * 4;
    for (int idx = t; idx < 4 * HD; idx += 256) {
        int nb = idx >> 7, k = idx & 127;
        float v = g_out1[(size_t)(n0 + nb) * HD + k];
        xs[nb][k] = v > 0.f ? v : 0.f;
    }
    __syncthreads();
    float acc[4] = {0,0,0,0};
#pragma unroll 4
    for (int k = 0; k < HD; k++) {
        float w = lw2[k * 256 + t];
#pragma unroll
        for (int nb = 0; nb < 4; nb++) acc[nb] = fmaf(xs[nb][k], w, acc[nb]);
    }
    float bias = b2[t];
#pragma unroll
    for (int nb = 0; nb < 4; nb++)
        g_out2[(size_t)(n0 + nb) * 256 + t] = acc[nb] + bias;
}

// ================= edge messages layer 2 ========================
__global__ void edge2_kernel(const int* __restrict__ src,
                             const int* __restrict__ dst,
                             const int* __restrict__ et,
                             const float* __restrict__ norm,
                             const float* __restrict__ W2) {
    int e = blockIdx.x * 8 + (threadIdx.x >> 5);
    if (e >= NEDGES) return;
    int l = threadIdx.x & 31;
    int s = src[e], d = dst[e], r = et[e];
    float nr = norm[e];
    const float* xrow = g_out1 + (size_t)s * HD;
    float4 xv = *(const float4*)(xrow + 4 * l);
    xv.x = xv.x > 0.f ? xv.x : 0.f;
    xv.y = xv.y > 0.f ? xv.y : 0.f;
    xv.z = xv.z > 0.f ? xv.z : 0.f;
    xv.w = xv.w > 0.f ? xv.w : 0.f;
    const float* w = W2 + (size_t)r * 512 + l * 16;  // [64][2][4] per rel
    float4 wa0 = *(const float4*)(w);
    float4 wa1 = *(const float4*)(w + 4);
    float4 wb0 = *(const float4*)(w + 8);
    float4 wb1 = *(const float4*)(w + 12);
    float m0 = (xv.x * wa0.x + xv.y * wa1.x) * nr;
    float m1 = (xv.x * wa0.y + xv.y * wa1.y) * nr;
    float m2 = (xv.x * wa0.z + xv.y * wa1.z) * nr;
    float m3 = (xv.x * wa0.w + xv.y * wa1.w) * nr;
    float m4 = (xv.z * wb0.x + xv.w * wb1.x) * nr;
    float m5 = (xv.z * wb0.y + xv.w * wb1.y) * nr;
    float m6 = (xv.z * wb0.z + xv.w * wb1.z) * nr;
    float m7 = (xv.z * wb0.w + xv.w * wb1.w) * nr;
    float* p = g_out2 + (size_t)d * 256 + 8 * l;
    red_add_v4(p,     m0, m1, m2, m3);
    red_add_v4(p + 4, m4, m5, m6, m7);
}

// ================= z = m + sqrt(softplus(hv)+1e-8)*eps ==========
__global__ void z_kernel(const float* __restrict__ eps) {
    int i = blockIdx.x * blockDim.x + threadIdx.x;   // over N*HD
    if (i >= NNODES * HD) return;
    int n = i >> 7, j = i & 127;
    float m  = g_out2[(size_t)n * 256 + j];
    float hv = g_out2[(size_t)n * 256 + 128 + j];
    float sp = fmaxf(hv, 0.f) + log1pf(expf(-fabsf(hv)));
    float v = sp + 1e-8f;
    g_z[i] = fmaf(sqrtf(v), eps[i], m);
}

// ================= hr = z[head] * w_rel[rel] ====================
__global__ void hr_kernel(const int* __restrict__ head_ids,
                          const int* __restrict__ rel_ids,
                          const float* __restrict__ w_rel) {
    int i = blockIdx.x * blockDim.x + threadIdx.x;   // over NQ*HD
    if (i >= NQ * HD) return;
    int b = i >> 7, j = i & 127;
    g_hr[i] = g_z[(size_t)head_ids[b] * HD + j] * w_rel[(size_t)rel_ids[b] * HD + j];
}

// ================= scores = hr @ z^T  [2048 x 20000] ============
// 128x128 tile per block, 256 threads, 8x8 per thread, BK=32, FFMA2
__global__ __launch_bounds__(256) void scores_kernel(float* __restrict__ C) {
    __shared__ float As[32][132];
    __shared__ float Bs[32][132];
    int tid = threadIdx.x;
    int tx = tid & 15;        // n-dim, 16 threads * 8 = 128
    int ty = tid >> 4;        // m-dim, 16 threads * 8 = 128
    int m0 = blockIdx.y * 128, n0 = blockIdx.x * 128;

    unsigned long long acc[8][4];
#pragma unroll
    for (int i = 0; i < 8; i++)
#pragma unroll
        for (int j = 0; j < 4; j++) acc[i][j] = 0ULL;

#pragma unroll
    for (int kk = 0; kk < HD; kk += 32) {
        // load A tile: 128 rows x 32 k = 1024 float4, 4 per thread
#pragma unroll
        for (int i = 0; i < 4; i++) {
            int idx = tid + i * 256;      // 0..1023
            int row = idx >> 3;           // 0..127
            int c   = idx & 7;            // k-quad 0..7
            float4 v = *(const float4*)(g_hr + (size_t)(m0 + row) * HD + kk + c * 4);
            As[c * 4 + 0][row] = v.x;
            As[c * 4 + 1][row] = v.y;
            As[c * 4 + 2][row] = v.z;
            As[c * 4 + 3][row] = v.w;
            int gn = n0 + row;
            float4 b = make_float4(0.f, 0.f, 0.f, 0.f);
            if (gn < NNODES)
                b = *(const float4*)(g_z + (size_t)gn * HD + kk + c * 4);
            Bs[c * 4 + 0][row] = b.x;
            Bs[c * 4 + 1][row] = b.y;
            Bs[c * 4 + 2][row] = b.z;
            Bs[c * 4 + 3][row] = b.w;
        }
        __syncthreads();
#pragma unroll
        for (int k = 0; k < 32; k++) {
            float4 a0 = *(float4*)(&As[k][ty * 8]);
            float4 a1 = *(float4*)(&As[k][ty * 8 + 4]);
            float4 b0 = *(float4*)(&Bs[k][tx * 8]);
            float4 b1 = *(float4*)(&Bs[k][tx * 8 + 4]);
            unsigned long long bp[4];
            bp[0] = pack2(b0.x, b0.y);
            bp[1] = pack2(b0.z, b0.w);
            bp[2] = pack2(b1.x, b1.y);
            bp[3] = pack2(b1.z, b1.w);
            float av[8] = {a0.x, a0.y, a0.z, a0.w, a1.x, a1.y, a1.z, a1.w};
#pragma unroll
            for (int i = 0; i < 8; i++) {
                unsigned long long ad = pack2(av[i], av[i]);
                ffma2(acc[i][0], ad, bp[0]);
                ffma2(acc[i][1], ad, bp[1]);
                ffma2(acc[i][2], ad, bp[2]);
                ffma2(acc[i][3], ad, bp[3]);
            }
        }
        __syncthreads();
    }

    // store 8x8 per thread as 2 float4 per row
#pragma unroll
    for (int i = 0; i < 8; i++) {
        int gm = m0 + ty * 8 + i;
        int gn = n0 + tx * 8;
        float2 c0 = unpack2(acc[i][0]);
        float2 c1 = unpack2(acc[i][1]);
        float2 c2 = unpack2(acc[i][2]);
        float2 c3 = unpack2(acc[i][3]);
        if (gn + 3 < NNODES)
            *(float4*)(C + (size_t)gm * NNODES + gn) = make_float4(c0.x, c0.y, c1.x, c1.y);
        else {
            if (gn + 0 < NNODES) C[(size_t)gm * NNODES + gn + 0] = c0.x;
            if (gn + 1 < NNODES) C[(size_t)gm * NNODES + gn + 1] = c0.y;
            if (gn + 2 < NNODES) C[(size_t)gm * NNODES + gn + 2] = c1.x;
        }
        if (gn + 7 < NNODES)
            *(float4*)(C + (size_t)gm * NNODES + gn + 4) = make_float4(c2.x, c2.y, c3.x, c3.y);
        else {
            if (gn + 4 < NNODES) C[(size_t)gm * NNODES + gn + 4] = c2.x;
            if (gn + 5 < NNODES) C[(size_t)gm * NNODES + gn + 5] = c2.y;
            if (gn + 6 < NNODES) C[(size_t)gm * NNODES + gn + 6] = c3.x;
        }
    }
}

// =================================================================
extern "C" void kernel_launch(void* const* d_in, const int* in_sizes, int n_in,
                              void* d_out, int out_size) {
    const int*   h        = (const int*)d_in[0];
    const int*   src      = (const int*)d_in[1];
    const int*   dst      = (const int*)d_in[2];
    const int*   etypes   = (const int*)d_in[3];
    const float* norm     = (const float*)d_in[4];
    const int*   head_ids = (const int*)d_in[5];
    const int*   rel_ids  = (const int*)d_in[6];
    const float* embed    = (const float*)d_in[7];
    const float* W1       = (const float*)d_in[8];
    const float* lw1      = (const float*)d_in[9];
    const float* b1       = (const float*)d_in[10];
    const float* W2       = (const float*)d_in[11];
    const float* lw2      = (const float*)d_in[12];
    const float* b2       = (const float*)d_in[13];
    const float* w_rel    = (const float*)d_in[14];
    const float* eps      = (const float*)d_in[15];
    float* out = (float*)d_out;

    selfloop1_kernel<<<NNODES / 8, 128>>>(embed, h, lw1, b1);
    edge1_kernel<<<NEDGES / 8, 256>>>(embed, h, src, dst, etypes, norm, W1);

    selfloop2_kernel<<<NNODES / 4, 256>>>(lw2, b2);
    edge2_kernel<<<NEDGES / 8, 256>>>(src, dst, etypes, norm, W2);

    z_kernel<<<(NNODES * HD + 255) / 256, 256>>>(eps);

    hr_kernel<<<(NQ * HD + 255) / 256, 256>>>(head_ids, rel_ids, w_rel);
    dim3 grid((NNODES + 127) / 128, NQ / 128);
    scores_kernel<<<grid, 256>>>(out);
}

// round 9
// speedup vs baseline: 1.5413x; 1.3073x over previous
#include <cuda_runtime.h>
#include <cuda_bf16.h>
#include <cstdint>

// Problem constants (fixed by the dataset)
#define NNODES 20000
#define NEDGES 256000
#define HD     128
#define NR     100
#define NB     64
#define NQ     2048   // B query pairs

// ---------------- scratch (no allocation allowed) ----------------
__device__ float g_out1[NNODES * HD];        // layer1 pre-activation
__device__ float g_out2[NNODES * 2 * HD];    // layer2 output
__device__ float g_z[NNODES * HD];           // latent (fp32, for hr gather)
__device__ __nv_bfloat16 g_z_hi[NNODES * HD];
__device__ __nv_bfloat16 g_z_lo[NNODES * HD];
__device__ __nv_bfloat16 g_hr_hi[NQ * HD];
__device__ __nv_bfloat16 g_hr_lo[NQ * HD];

// ---------------- vectorized global reduction -------------------
__device__ __forceinline__ void red_add_v4(float* p, float a, float b, float c, float d) {
    asm volatile("red.global.v4.f32.add [%0], {%1,%2,%3,%4};"
                 :: "l"(p), "f"(a), "f"(b), "f"(c), "f"(d) : "memory");
}

__device__ __forceinline__ uint32_t smem_to_u32(const void* p) {
    uint32_t a;
    asm("{ .reg .u64 t; cvta.to.shared.u64 t, %1; cvt.u32.u64 %0, t; }" : "=r"(a) : "l"(p));
    return a;
}

// ldmatrix x4 (no trans)
__device__ __forceinline__ void ldsm_x4(uint32_t addr, uint32_t* r) {
    asm volatile("ldmatrix.sync.aligned.m8n8.x4.shared.b16 {%0,%1,%2,%3}, [%4];"
                 : "=r"(r[0]), "=r"(r[1]), "=r"(r[2]), "=r"(r[3]) : "r"(addr));
}
// bf16 mma: D(f32) += A(bf16) * B(bf16)
__device__ __forceinline__ void mma_bf16(float* c, const uint32_t* a, const uint32_t* b) {
    asm volatile(
        "mma.sync.aligned.m16n8k16.row.col.f32.bf16.bf16.f32 "
        "{%0,%1,%2,%3}, {%4,%5,%6,%7}, {%8,%9}, {%0,%1,%2,%3};"
        : "+f"(c[0]), "+f"(c[1]), "+f"(c[2]), "+f"(c[3])
        : "r"(a[0]), "r"(a[1]), "r"(a[2]), "r"(a[3]), "r"(b[0]), "r"(b[1]));
}

// bf16 split: x = hi + lo (hi = rn(x), lo = rn(x - hi))
__device__ __forceinline__ void split_bf16(float x, __nv_bfloat16& hi, __nv_bfloat16& lo) {
    hi = __float2bfloat16(x);
    lo = __float2bfloat16(x - __bfloat162float(hi));
}

// ================= self-loop layer 1: out1 = X@lw1 + b1 =========
__global__ void selfloop1_kernel(const float* __restrict__ embed,
                                 const int* __restrict__ h,
                                 const float* __restrict__ lw1,
                                 const float* __restrict__ b1) {
    __shared__ float xs[8][HD];
    int t = threadIdx.x;
    int n0 = blockIdx.x * 8;
#pragma unroll
    for (int nb = 0; nb < 8; nb++) {
        int node = n0 + nb;
        xs[nb][t] = embed[(size_t)h[node] * HD + t];
    }
    __syncthreads();
    float acc[8] = {0,0,0,0,0,0,0,0};
#pragma unroll 4
    for (int k = 0; k < HD; k++) {
        float w = lw1[k * HD + t];
#pragma unroll
        for (int nb = 0; nb < 8; nb++) acc[nb] = fmaf(xs[nb][k], w, acc[nb]);
    }
    float bias = b1[t];
#pragma unroll
    for (int nb = 0; nb < 8; nb++)
        g_out1[(size_t)(n0 + nb) * HD + t] = acc[nb] + bias;
}

// ================= edge messages layer 1 (atomic scatter) =======
__global__ void edge1_kernel(const float* __restrict__ embed,
                             const int* __restrict__ h,
                             const int* __restrict__ src,
                             const int* __restrict__ dst,
                             const int* __restrict__ et,
                             const float* __restrict__ norm,
                             const float* __restrict__ W1) {
    int e = blockIdx.x * 8 + (threadIdx.x >> 5);
    if (e >= NEDGES) return;
    int l = threadIdx.x & 31;
    int s = src[e], d = dst[e], r = et[e];
    float nr = norm[e];
    const float* xrow = embed + (size_t)h[s] * HD;
    float4 xv = *(const float4*)(xrow + 4 * l);
    const float* w = W1 + (size_t)r * 256 + l * 8;   // [64][2][2] per rel
    float4 w0 = *(const float4*)(w);
    float4 w1 = *(const float4*)(w + 4);
    float m0 = (xv.x * w0.x + xv.y * w0.z) * nr;
    float m1 = (xv.x * w0.y + xv.y * w0.w) * nr;
    float m2 = (xv.z * w1.x + xv.w * w1.z) * nr;
    float m3 = (xv.z * w1.y + xv.w * w1.w) * nr;
    red_add_v4(g_out1 + (size_t)d * HD + 4 * l, m0, m1, m2, m3);
}

// ================= self-loop layer 2: out2 = relu(out1)@lw2 + b2
__global__ void selfloop2_kernel(const float* __restrict__ lw2,
                                 const float* __restrict__ b2) {
    __shared__ float xs[4][HD];
    int t = threadIdx.x;
    int n0 = blockIdx.x * 4;
    for (int idx = t; idx < 4 * HD; idx += 256) {
        int nb = idx >> 7, k = idx & 127;
        float v = g_out1[(size_t)(n0 + nb) * HD + k];
        xs[nb][k] = v > 0.f ? v : 0.f;
    }
    __syncthreads();
    float acc[4] = {0,0,0,0};
#pragma unroll 4
    for (int k = 0; k < HD; k++) {
        float w = lw2[k * 256 + t];
#pragma unroll
        for (int nb = 0; nb < 4; nb++) acc[nb] = fmaf(xs[nb][k], w, acc[nb]);
    }
    float bias = b2[t];
#pragma unroll
    for (int nb = 0; nb < 4; nb++)
        g_out2[(size_t)(n0 + nb) * 256 + t] = acc[nb] + bias;
}

// ================= edge messages layer 2 ========================
__global__ void edge2_kernel(const int* __restrict__ src,
                             const int* __restrict__ dst,
                             const int* __restrict__ et,
                             const float* __restrict__ norm,
                             const float* __restrict__ W2) {
    int e = blockIdx.x * 8 + (threadIdx.x >> 5);
    if (e >= NEDGES) return;
    int l = threadIdx.x & 31;
    int s = src[e], d = dst[e], r = et[e];
    float nr = norm[e];
    const float* xrow = g_out1 + (size_t)s * HD;
    float4 xv = *(const float4*)(xrow + 4 * l);
    xv.x = xv.x > 0.f ? xv.x : 0.f;
    xv.y = xv.y > 0.f ? xv.y : 0.f;
    xv.z = xv.z > 0.f ? xv.z : 0.f;
    xv.w = xv.w > 0.f ? xv.w : 0.f;
    const float* w = W2 + (size_t)r * 512 + l * 16;  // [64][2][4] per rel
    float4 wa0 = *(const float4*)(w);
    float4 wa1 = *(const float4*)(w + 4);
    float4 wb0 = *(const float4*)(w + 8);
    float4 wb1 = *(const float4*)(w + 12);
    float m0 = (xv.x * wa0.x + xv.y * wa1.x) * nr;
    float m1 = (xv.x * wa0.y + xv.y * wa1.y) * nr;
    float m2 = (xv.x * wa0.z + xv.y * wa1.z) * nr;
    float m3 = (xv.x * wa0.w + xv.y * wa1.w) * nr;
    float m4 = (xv.z * wb0.x + xv.w * wb1.x) * nr;
    float m5 = (xv.z * wb0.y + xv.w * wb1.y) * nr;
    float m6 = (xv.z * wb0.z + xv.w * wb1.z) * nr;
    float m7 = (xv.z * wb0.w + xv.w * wb1.w) * nr;
    float* p = g_out2 + (size_t)d * 256 + 8 * l;
    red_add_v4(p,     m0, m1, m2, m3);
    red_add_v4(p + 4, m4, m5, m6, m7);
}

// ====== z = m + sqrt(softplus(hv)+1e-8)*eps; also split to bf16 ==
__global__ void z_kernel(const float* __restrict__ eps) {
    int i = blockIdx.x * blockDim.x + threadIdx.x;   // over N*HD
    if (i >= NNODES * HD) return;
    int n = i >> 7, j = i & 127;
    float m  = g_out2[(size_t)n * 256 + j];
    float hv = g_out2[(size_t)n * 256 + 128 + j];
    float sp = fmaxf(hv, 0.f) + log1pf(expf(-fabsf(hv)));
    float v = sp + 1e-8f;
    float z = fmaf(sqrtf(v), eps[i], m);
    g_z[i] = z;
    __nv_bfloat16 hi, lo;
    split_bf16(z, hi, lo);
    g_z_hi[i] = hi;
    g_z_lo[i] = lo;
}

// ====== hr = z[head] * w_rel[rel], split to bf16 ================
__global__ void hr_kernel(const int* __restrict__ head_ids,
                          const int* __restrict__ rel_ids,
                          const float* __restrict__ w_rel) {
    int i = blockIdx.x * blockDim.x + threadIdx.x;   // over NQ*HD
    if (i >= NQ * HD) return;
    int b = i >> 7, j = i & 127;
    float hr = g_z[(size_t)head_ids[b] * HD + j] * w_rel[(size_t)rel_ids[b] * HD + j];
    __nv_bfloat16 hi, lo;
    split_bf16(hr, hi, lo);
    g_hr_hi[i] = hi;
    g_hr_lo[i] = lo;
}

// ================= scores = hr @ z^T via mma.sync (bf16 split) ==
// Tile 128x128 per CTA, 8 warps (2x4), warp tile 64x32, K=128 resident.
// smem rows padded to 136 bf16 (272B): ldmatrix conflict-free.
#define TM 128
#define TN 128
#define PAD_K   136
#define TILE_B  (128 * PAD_K * 2)          // 34816 bytes per buffer
#define S2_A_HI 0
#define S2_A_LO (S2_A_HI + TILE_B)
#define S2_B_HI (S2_A_LO + TILE_B)
#define S2_B_LO (S2_B_HI + TILE_B)
#define S2_TOTAL (4 * TILE_B)              // 139264 bytes

__global__ __launch_bounds__(256, 1) void scores_mma_kernel(float* __restrict__ C) {
    extern __shared__ char smem[];
    uint32_t sb = smem_to_u32(smem);
    int tid = threadIdx.x;
    int wid = tid >> 5, lid = tid & 31;
    int m0 = blockIdx.y * TM;
    int n0 = blockIdx.x * TN;

    // ---- stage tiles gmem(bf16) -> smem (padded rows) ----
    // each tile: 128 rows x 16 chunks of 16B
    for (int u = tid; u < 2048; u += 256) {
        int row = u >> 4, ch = u & 15;
        uint32_t so = (uint32_t)row * (PAD_K * 2) + ch * 16;
        size_t ga = (size_t)(m0 + row) * HD + ch * 8;
        *(uint4*)(smem + S2_A_HI + so) = *(const uint4*)(g_hr_hi + ga);
        *(uint4*)(smem + S2_A_LO + so) = *(const uint4*)(g_hr_lo + ga);
        int gn = n0 + row;
        uint4 bh = make_uint4(0, 0, 0, 0), bl = make_uint4(0, 0, 0, 0);
        if (gn < NNODES) {
            size_t gb = (size_t)gn * HD + ch * 8;
            bh = *(const uint4*)(g_z_hi + gb);
            bl = *(const uint4*)(g_z_lo + gb);
        }
        *(uint4*)(smem + S2_B_HI + so) = bh;
        *(uint4*)(smem + S2_B_LO + so) = bl;
    }
    __syncthreads();

    int wm = (wid & 1) * 64;        // warp m offset within tile
    int wn = (wid >> 1) * 32;       // warp n offset within tile
    int r8 = lid & 7, g = lid >> 3;

    // per-lane ldmatrix address offsets (bytes)
    // A x4: g0:(m r8,k0) g1:(m 8+r8,k0) g2:(m r8,k+8) g3:(m 8+r8,k+8)
    uint32_t a_off = (uint32_t)((g & 1) * 8 + r8) * (PAD_K * 2) + (uint32_t)(g >> 1) * 16;
    // B x4: g0:(n r8,k0) g1:(n r8,k+8) g2:(n 8+r8,k0) g3:(n 8+r8,k+8)
    uint32_t b_off = (uint32_t)((g >> 1) * 8 + r8) * (PAD_K * 2) + (uint32_t)(g & 1) * 16;

    float acc[4][4][4];
#pragma unroll
    for (int i = 0; i < 4; i++)
#pragma unroll
        for (int j = 0; j < 4; j++)
#pragma unroll
            for (int q = 0; q < 4; q++) acc[i][j][q] = 0.f;

    const uint32_t aBase[3] = { sb + S2_A_HI, sb + S2_A_HI, sb + S2_A_LO };
    const uint32_t bBase[3] = { sb + S2_B_HI, sb + S2_B_LO, sb + S2_B_HI };

#pragma unroll
    for (int pass = 0; pass < 3; pass++) {
        uint32_t aB = aBase[pass] + (uint32_t)wm * (PAD_K * 2) + a_off;
        uint32_t bB = bBase[pass] + (uint32_t)wn * (PAD_K * 2) + b_off;
#pragma unroll
        for (int kk = 0; kk < 8; kk++) {
            uint32_t af[4][4], bf[2][4];
#pragma unroll
            for (int mi = 0; mi < 4; mi++)
                ldsm_x4(aB + (uint32_t)mi * 16 * (PAD_K * 2) + kk * 32, af[mi]);
#pragma unroll
            for (int nj = 0; nj < 2; nj++)
                ldsm_x4(bB + (uint32_t)nj * 16 * (PAD_K * 2) + kk * 32, bf[nj]);
#pragma unroll
            for (int mi = 0; mi < 4; mi++) {
#pragma unroll
                for (int nf = 0; nf < 4; nf++)
                    mma_bf16(acc[mi][nf], af[mi], &bf[nf >> 1][(nf & 1) * 2]);
            }
        }
    }

    // ---- epilogue: direct stores ----
    int mrow = lid >> 2;            // 0..7
    int ncol = (lid & 3) * 2;       // 0,2,4,6
#pragma unroll
    for (int mi = 0; mi < 4; mi++) {
#pragma unroll
        for (int nf = 0; nf < 4; nf++) {
            int gm = m0 + wm + mi * 16 + mrow;
            int gn = n0 + wn + nf * 8 + ncol;
            if (gn < NNODES) {  // gn even, NNODES even -> pair fully valid
                *(float2*)(C + (size_t)gm * NNODES + gn) =
                    make_float2(acc[mi][nf][0], acc[mi][nf][1]);
                *(float2*)(C + (size_t)(gm + 8) * NNODES + gn) =
                    make_float2(acc[mi][nf][2], acc[mi][nf][3]);
            }
        }
    }
}

// =================================================================
extern "C" void kernel_launch(void* const* d_in, const int* in_sizes, int n_in,
                              void* d_out, int out_size) {
    const int*   h        = (const int*)d_in[0];
    const int*   src      = (const int*)d_in[1];
    const int*   dst      = (const int*)d_in[2];
    const int*   etypes   = (const int*)d_in[3];
    const float* norm     = (const float*)d_in[4];
    const int*   head_ids = (const int*)d_in[5];
    const int*   rel_ids  = (const int*)d_in[6];
    const float* embed    = (const float*)d_in[7];
    const float* W1       = (const float*)d_in[8];
    const float* lw1      = (const float*)d_in[9];
    const float* b1       = (const float*)d_in[10];
    const float* W2       = (const float*)d_in[11];
    const float* lw2      = (const float*)d_in[12];
    const float* b2       = (const float*)d_in[13];
    const float* w_rel    = (const float*)d_in[14];
    const float* eps      = (const float*)d_in[15];
    float* out = (float*)d_out;

    cudaFuncSetAttribute(scores_mma_kernel,
                         cudaFuncAttributeMaxDynamicSharedMemorySize, S2_TOTAL);

    selfloop1_kernel<<<NNODES / 8, 128>>>(embed, h, lw1, b1);
    edge1_kernel<<<NEDGES / 8, 256>>>(embed, h, src, dst, etypes, norm, W1);

    selfloop2_kernel<<<NNODES / 4, 256>>>(lw2, b2);
    edge2_kernel<<<NEDGES / 8, 256>>>(src, dst, etypes, norm, W2);

    z_kernel<<<(NNODES * HD + 255) / 256, 256>>>(eps);

    hr_kernel<<<(NQ * HD + 255) / 256, 256>>>(head_ids, rel_ids, w_rel);

    dim3 grid((NNODES + TN - 1) / TN, NQ / TM);
    scores_mma_kernel<<<grid, 256, S2_TOTAL>>>(out);
}

// round 14
// speedup vs baseline: 1.5687x; 1.0178x over previous
#include <cuda_runtime.h>
#include <cuda_bf16.h>
#include <cstdint>

// Problem constants (fixed by the dataset)
#define NNODES 20000
#define NEDGES 256000
#define HD     128
#define NR     100
#define NB     64
#define NQ     2048   // B query pairs

// ---------------- scratch (no allocation allowed) ----------------
__device__ float g_out1[NNODES * HD];        // layer1 pre-activation
__device__ float g_out2[NNODES * 2 * HD];    // layer2 output
__device__ float g_z[NNODES * HD];           // latent (fp32, for hr gather)
__device__ __nv_bfloat16 g_z_hi[NNODES * HD];
__device__ __nv_bfloat16 g_z_lo[NNODES * HD];
__device__ __nv_bfloat16 g_hr_hi[NQ * HD];
__device__ __nv_bfloat16 g_hr_lo[NQ * HD];

// ---------------- vectorized global reduction -------------------
__device__ __forceinline__ void red_add_v4(float* p, float a, float b, float c, float d) {
    asm volatile("red.global.v4.f32.add [%0], {%1,%2,%3,%4};"
                 :: "l"(p), "f"(a), "f"(b), "f"(c), "f"(d) : "memory");
}

__device__ __forceinline__ uint32_t smem_to_u32(const void* p) {
    uint32_t a;
    asm("{ .reg .u64 t; cvta.to.shared.u64 t, %1; cvt.u32.u64 %0, t; }" : "=r"(a) : "l"(p));
    return a;
}

// ldmatrix x4 (no trans)
__device__ __forceinline__ void ldsm_x4(uint32_t addr, uint32_t* r) {
    asm volatile("ldmatrix.sync.aligned.m8n8.x4.shared.b16 {%0,%1,%2,%3}, [%4];"
                 : "=r"(r[0]), "=r"(r[1]), "=r"(r[2]), "=r"(r[3]) : "r"(addr));
}
// bf16 mma: D(f32) += A(bf16) * B(bf16)
__device__ __forceinline__ void mma_bf16(float* c, const uint32_t* a, const uint32_t* b) {
    asm volatile(
        "mma.sync.aligned.m16n8k16.row.col.f32.bf16.bf16.f32 "
        "{%0,%1,%2,%3}, {%4,%5,%6,%7}, {%8,%9}, {%0,%1,%2,%3};"
        : "+f"(c[0]), "+f"(c[1]), "+f"(c[2]), "+f"(c[3])
        : "r"(a[0]), "r"(a[1]), "r"(a[2]), "r"(a[3]), "r"(b[0]), "r"(b[1]));
}

// bf16 split: x = hi + lo (hi = rn(x), lo = rn(x - hi))
__device__ __forceinline__ void split_bf16(float x, __nv_bfloat16& hi, __nv_bfloat16& lo) {
    hi = __float2bfloat16(x);
    lo = __float2bfloat16(x - __bfloat162float(hi));
}

// ================= self-loop layer 1: out1 = X@lw1 + b1 =========
__global__ void selfloop1_kernel(const float* __restrict__ embed,
                                 const int* __restrict__ h,
                                 const float* __restrict__ lw1,
                                 const float* __restrict__ b1) {
    __shared__ float xs[8][HD];
    int t = threadIdx.x;
    int n0 = blockIdx.x * 8;
#pragma unroll
    for (int nb = 0; nb < 8; nb++) {
        int node = n0 + nb;
        xs[nb][t] = embed[(size_t)h[node] * HD + t];
    }
    __syncthreads();
    float acc[8] = {0,0,0,0,0,0,0,0};
#pragma unroll 4
    for (int k = 0; k < HD; k++) {
        float w = lw1[k * HD + t];
#pragma unroll
        for (int nb = 0; nb < 8; nb++) acc[nb] = fmaf(xs[nb][k], w, acc[nb]);
    }
    float bias = b1[t];
#pragma unroll
    for (int nb = 0; nb < 8; nb++)
        g_out1[(size_t)(n0 + nb) * HD + t] = acc[nb] + bias;
}

// ================= edge messages layer 1 (4 edges per warp) =====
__global__ __launch_bounds__(256) void edge1_kernel(
        const float* __restrict__ embed,
        const int* __restrict__ h,
        const int* __restrict__ src,
        const int* __restrict__ dst,
        const int* __restrict__ et,
        const float* __restrict__ norm,
        const float* __restrict__ W1) {
    int w = blockIdx.x * 8 + (threadIdx.x >> 5);
    int l = threadIdx.x & 31;
    int e0 = w * 4;                           // NEDGES % 32 == 0 -> always in range
    int s[4], d[4], r[4];
    float nr[4];
#pragma unroll
    for (int i = 0; i < 4; i++) {
        int e = e0 + i;
        s[i] = src[e]; d[i] = dst[e]; r[i] = et[e]; nr[i] = norm[e];
    }
    int hs[4];
#pragma unroll
    for (int i = 0; i < 4; i++) hs[i] = h[s[i]];
    float4 xv[4];
#pragma unroll
    for (int i = 0; i < 4; i++)
        xv[i] = *(const float4*)(embed + (size_t)hs[i] * HD + 4 * l);
    float4 w0[4], w1[4];
#pragma unroll
    for (int i = 0; i < 4; i++) {
        const float* wp = W1 + (size_t)r[i] * 256 + l * 8;   // [64][2][2] per rel
        w0[i] = *(const float4*)(wp);
        w1[i] = *(const float4*)(wp + 4);
    }
#pragma unroll
    for (int i = 0; i < 4; i++) {
        float m0 = (xv[i].x * w0[i].x + xv[i].y * w0[i].z) * nr[i];
        float m1 = (xv[i].x * w0[i].y + xv[i].y * w0[i].w) * nr[i];
        float m2 = (xv[i].z * w1[i].x + xv[i].w * w1[i].z) * nr[i];
        float m3 = (xv[i].z * w1[i].y + xv[i].w * w1[i].w) * nr[i];
        red_add_v4(g_out1 + (size_t)d[i] * HD + 4 * l, m0, m1, m2, m3);
    }
}

// ================= self-loop layer 2: out2 = relu(out1)@lw2 + b2
__global__ void selfloop2_kernel(const float* __restrict__ lw2,
                                 const float* __restrict__ b2) {
    __shared__ float xs[4][HD];
    int t = threadIdx.x;
    int n0 = blockIdx.x * 4;
    for (int idx = t; idx < 4 * HD; idx += 256) {
        int nb = idx >> 7, k = idx & 127;
        float v = g_out1[(size_t)(n0 + nb) * HD + k];
        xs[nb][k] = v > 0.f ? v : 0.f;
    }
    __syncthreads();
    float acc[4] = {0,0,0,0};
#pragma unroll 4
    for (int k = 0; k < HD; k++) {
        float w = lw2[k * 256 + t];
#pragma unroll
        for (int nb = 0; nb < 4; nb++) acc[nb] = fmaf(xs[nb][k], w, acc[nb]);
    }
    float bias = b2[t];
#pragma unroll
    for (int nb = 0; nb < 4; nb++)
        g_out2[(size_t)(n0 + nb) * 256 + t] = acc[nb] + bias;
}

// ================= edge messages layer 2 (4 edges per warp) =====
__global__ __launch_bounds__(256) void edge2_kernel(
        const int* __restrict__ src,
        const int* __restrict__ dst,
        const int* __restrict__ et,
        const float* __restrict__ norm,
        const float* __restrict__ W2) {
    int w = blockIdx.x * 8 + (threadIdx.x >> 5);
    int l = threadIdx.x & 31;
    int e0 = w * 4;
    int s[4], d[4], r[4];
    float nr[4];
#pragma unroll
    for (int i = 0; i < 4; i++) {
        int e = e0 + i;
        s[i] = src[e]; d[i] = dst[e]; r[i] = et[e]; nr[i] = norm[e];
    }
    float4 xv[4];
#pragma unroll
    for (int i = 0; i < 4; i++) {
        float4 v = *(const float4*)(g_out1 + (size_t)s[i] * HD + 4 * l);
        v.x = v.x > 0.f ? v.x : 0.f;
        v.y = v.y > 0.f ? v.y : 0.f;
        v.z = v.z > 0.f ? v.z : 0.f;
        v.w = v.w > 0.f ? v.w : 0.f;
        xv[i] = v;
    }
#pragma unroll
    for (int i = 0; i < 4; i++) {
        const float* wp = W2 + (size_t)r[i] * 512 + l * 16;  // [64][2][4] per rel
        float4 wa0 = *(const float4*)(wp);
        float4 wa1 = *(const float4*)(wp + 4);
        float4 wb0 = *(const float4*)(wp + 8);
        float4 wb1 = *(const float4*)(wp + 12);
        float m0 = (xv[i].x * wa0.x + xv[i].y * wa1.x) * nr[i];
        float m1 = (xv[i].x * wa0.y + xv[i].y * wa1.y) * nr[i];
        float m2 = (xv[i].x * wa0.z + xv[i].y * wa1.z) * nr[i];
        float m3 = (xv[i].x * wa0.w + xv[i].y * wa1.w) * nr[i];
        float m4 = (xv[i].z * wb0.x + xv[i].w * wb1.x) * nr[i];
        float m5 = (xv[i].z * wb0.y + xv[i].w * wb1.y) * nr[i];
        float m6 = (xv[i].z * wb0.z + xv[i].w * wb1.z) * nr[i];
        float m7 = (xv[i].z * wb0.w + xv[i].w * wb1.w) * nr[i];
        float* p = g_out2 + (size_t)d[i] * 256 + 8 * l;
        red_add_v4(p,     m0, m1, m2, m3);
        red_add_v4(p + 4, m4, m5, m6, m7);
    }
}

// ====== z = m + sqrt(softplus(hv)+1e-8)*eps; also split to bf16 ==
__global__ void z_kernel(const float* __restrict__ eps) {
    int i = blockIdx.x * blockDim.x + threadIdx.x;   // over N*HD
    if (i >= NNODES * HD) return;
    int n = i >> 7, j = i & 127;
    float m  = g_out2[(size_t)n * 256 + j];
    float hv = g_out2[(size_t)n * 256 + 128 + j];
    float sp = fmaxf(hv, 0.f) + log1pf(expf(-fabsf(hv)));
    float v = sp + 1e-8f;
    float z = fmaf(sqrtf(v), eps[i], m);
    g_z[i] = z;
    __nv_bfloat16 hi, lo;
    split_bf16(z, hi, lo);
    g_z_hi[i] = hi;
    g_z_lo[i] = lo;
}

// ====== hr = z[head] * w_rel[rel], split to bf16 ================
__global__ void hr_kernel(const int* __restrict__ head_ids,
                          const int* __restrict__ rel_ids,
                          const float* __restrict__ w_rel) {
    int i = blockIdx.x * blockDim.x + threadIdx.x;   // over NQ*HD
    if (i >= NQ * HD) return;
    int b = i >> 7, j = i & 127;
    float hr = g_z[(size_t)head_ids[b] * HD + j] * w_rel[(size_t)rel_ids[b] * HD + j];
    __nv_bfloat16 hi, lo;
    split_bf16(hr, hi, lo);
    g_hr_hi[i] = hi;
    g_hr_lo[i] = lo;
}

// ================= scores = hr @ z^T via mma.sync (bf16 split) ==
// Tile 128x128 per CTA, 8 warps (2x4), warp tile 64x32, K=128 resident.
// smem rows padded to 136 bf16 (272B): ldmatrix conflict-free.
#define TM 128
#define TN 128
#define PAD_K   136
#define TILE_B  (128 * PAD_K * 2)          // 34816 bytes per buffer
#define S2_A_HI 0
#define S2_A_LO (S2_A_HI + TILE_B)
#define S2_B_HI (S2_A_LO + TILE_B)
#define S2_B_LO (S2_B_HI + TILE_B)
#define S2_TOTAL (4 * TILE_B)              // 139264 bytes

__global__ __launch_bounds__(256, 1) void scores_mma_kernel(float* __restrict__ C) {
    extern __shared__ char smem[];
    uint32_t sb = smem_to_u32(smem);
    int tid = threadIdx.x;
    int wid = tid >> 5, lid = tid & 31;
    int m0 = blockIdx.y * TM;
    int n0 = blockIdx.x * TN;

    // ---- stage tiles gmem(bf16) -> smem (padded rows) ----
    for (int u = tid; u < 2048; u += 256) {
        int row = u >> 4, ch = u & 15;
        uint32_t so = (uint32_t)row * (PAD_K * 2) + ch * 16;
        size_t ga = (size_t)(m0 + row) * HD + ch * 8;
        *(uint4*)(smem + S2_A_HI + so) = *(const uint4*)(g_hr_hi + ga);
        *(uint4*)(smem + S2_A_LO + so) = *(const uint4*)(g_hr_lo + ga);
        int gn = n0 + row;
        uint4 bh = make_uint4(0, 0, 0, 0), bl = make_uint4(0, 0, 0, 0);
        if (gn < NNODES) {
            size_t gb = (size_t)gn * HD + ch * 8;
            bh = *(const uint4*)(g_z_hi + gb);
            bl = *(const uint4*)(g_z_lo + gb);
        }
        *(uint4*)(smem + S2_B_HI + so) = bh;
        *(uint4*)(smem + S2_B_LO + so) = bl;
    }
    __syncthreads();

    int wm = (wid & 1) * 64;        // warp m offset within tile
    int wn = (wid >> 1) * 32;       // warp n offset within tile
    int r8 = lid & 7, g = lid >> 3;

    uint32_t a_off = (uint32_t)((g & 1) * 8 + r8) * (PAD_K * 2) + (uint32_t)(g >> 1) * 16;
    uint32_t b_off = (uint32_t)((g >> 1) * 8 + r8) * (PAD_K * 2) + (uint32_t)(g & 1) * 16;

    float acc[4][4][4];
#pragma unroll
    for (int i = 0; i < 4; i++)
#pragma unroll
        for (int j = 0; j < 4; j++)
#pragma unroll
            for (int q = 0; q < 4; q++) acc[i][j][q] = 0.f;

    const uint32_t aBase[3] = { sb + S2_A_HI, sb + S2_A_HI, sb + S2_A_LO };
    const uint32_t bBase[3] = { sb + S2_B_HI, sb + S2_B_LO, sb + S2_B_HI };

#pragma unroll
    for (int pass = 0; pass < 3; pass++) {
        uint32_t aB = aBase[pass] + (uint32_t)wm * (PAD_K * 2) + a_off;
        uint32_t bB = bBase[pass] + (uint32_t)wn * (PAD_K * 2) + b_off;
#pragma unroll
        for (int kk = 0; kk < 8; kk++) {
            uint32_t af[4][4], bf[2][4];
#pragma unroll
            for (int mi = 0; mi < 4; mi++)
                ldsm_x4(aB + (uint32_t)mi * 16 * (PAD_K * 2) + kk * 32, af[mi]);
#pragma unroll
            for (int nj = 0; nj < 2; nj++)
                ldsm_x4(bB + (uint32_t)nj * 16 * (PAD_K * 2) + kk * 32, bf[nj]);
#pragma unroll
            for (int mi = 0; mi < 4; mi++) {
#pragma unroll
                for (int nf = 0; nf < 4; nf++)
                    mma_bf16(acc[mi][nf], af[mi], &bf[nf >> 1][(nf & 1) * 2]);
            }
        }
    }

    // ---- epilogue: direct stores ----
    int mrow = lid >> 2;            // 0..7
    int ncol = (lid & 3) * 2;       // 0,2,4,6
#pragma unroll
    for (int mi = 0; mi < 4; mi++) {
#pragma unroll
        for (int nf = 0; nf < 4; nf++) {
            int gm = m0 + wm + mi * 16 + mrow;
            int gn = n0 + wn + nf * 8 + ncol;
            if (gn < NNODES) {
                *(float2*)(C + (size_t)gm * NNODES + gn) =
                    make_float2(acc[mi][nf][0], acc[mi][nf][1]);
                *(float2*)(C + (size_t)(gm + 8) * NNODES + gn) =
                    make_float2(acc[mi][nf][2], acc[mi][nf][3]);
            }
        }
    }
}

// =================================================================
extern "C" void kernel_launch(void* const* d_in, const int* in_sizes, int n_in,
                              void* d_out, int out_size) {
    const int*   h        = (const int*)d_in[0];
    const int*   src      = (const int*)d_in[1];
    const int*   dst      = (const int*)d_in[2];
    const int*   etypes   = (const int*)d_in[3];
    const float* norm     = (const float*)d_in[4];
    const int*   head_ids = (const int*)d_in[5];
    const int*   rel_ids  = (const int*)d_in[6];
    const float* embed    = (const float*)d_in[7];
    const float* W1       = (const float*)d_in[8];
    const float* lw1      = (const float*)d_in[9];
    const float* b1       = (const float*)d_in[10];
    const float* W2       = (const float*)d_in[11];
    const float* lw2      = (const float*)d_in[12];
    const float* b2       = (const float*)d_in[13];
    const float* w_rel    = (const float*)d_in[14];
    const float* eps      = (const float*)d_in[15];
    float* out = (float*)d_out;

    cudaFuncSetAttribute(scores_mma_kernel,
                         cudaFuncAttributeMaxDynamicSharedMemorySize, S2_TOTAL);

    selfloop1_kernel<<<NNODES / 8, 128>>>(embed, h, lw1, b1);
    edge1_kernel<<<NEDGES / 32, 256>>>(embed, h, src, dst, etypes, norm, W1);

    selfloop2_kernel<<<NNODES / 4, 256>>>(lw2, b2);
    edge2_kernel<<<NEDGES / 32, 256>>>(src, dst, etypes, norm, W2);

    z_kernel<<<(NNODES * HD + 255) / 256, 256>>>(eps);

    hr_kernel<<<(NQ * HD + 255) / 256, 256>>>(head_ids, rel_ids, w_rel);

    dim3 grid((NNODES + TN - 1) / TN, NQ / TM);
    scores_mma_kernel<<<grid, 256, S2_TOTAL>>>(out);
}

// round 15
// speedup vs baseline: 1.6017x; 1.0210x over previous
#include <cuda_runtime.h>
#include <cuda_bf16.h>
#include <cstdint>

// Problem constants (fixed by the dataset)
#define NNODES 20000
#define NEDGES 256000
#define HD     128
#define NR     100
#define NB     64
#define NQ     2048   // B query pairs

// ---------------- scratch (no allocation allowed) ----------------
__device__ float g_out1[NNODES * HD];        // layer1 pre-activation
__device__ float g_out2[NNODES * 2 * HD];    // layer2 output
__device__ float g_z[NNODES * HD];           // latent (fp32, for hr gather)
__device__ __nv_bfloat16 g_z_hi[NNODES * HD];
__device__ __nv_bfloat16 g_z_lo[NNODES * HD];
__device__ __nv_bfloat16 g_hr_hi[NQ * HD];
__device__ __nv_bfloat16 g_hr_lo[NQ * HD];
// relation bucketing
__device__ int g_rel_cnt[NR];
__device__ int g_rel_cur[NR];
__device__ int g_perm[NEDGES];

// ---------------- vectorized global reduction -------------------
__device__ __forceinline__ void red_add_v4(float* p, float a, float b, float c, float d) {
    asm volatile("red.global.v4.f32.add [%0], {%1,%2,%3,%4};"
                 :: "l"(p), "f"(a), "f"(b), "f"(c), "f"(d) : "memory");
}

__device__ __forceinline__ uint32_t smem_to_u32(const void* p) {
    uint32_t a;
    asm("{ .reg .u64 t; cvta.to.shared.u64 t, %1; cvt.u32.u64 %0, t; }" : "=r"(a) : "l"(p));
    return a;
}

// ldmatrix x4 (no trans)
__device__ __forceinline__ void ldsm_x4(uint32_t addr, uint32_t* r) {
    asm volatile("ldmatrix.sync.aligned.m8n8.x4.shared.b16 {%0,%1,%2,%3}, [%4];"
                 : "=r"(r[0]), "=r"(r[1]), "=r"(r[2]), "=r"(r[3]) : "r"(addr));
}
// bf16 mma: D(f32) += A(bf16) * B(bf16)
__device__ __forceinline__ void mma_bf16(float* c, const uint32_t* a, const uint32_t* b) {
    asm volatile(
        "mma.sync.aligned.m16n8k16.row.col.f32.bf16.bf16.f32 "
        "{%0,%1,%2,%3}, {%4,%5,%6,%7}, {%8,%9}, {%0,%1,%2,%3};"
        : "+f"(c[0]), "+f"(c[1]), "+f"(c[2]), "+f"(c[3])
        : "r"(a[0]), "r"(a[1]), "r"(a[2]), "r"(a[3]), "r"(b[0]), "r"(b[1]));
}

// bf16 split: x = hi + lo (hi = rn(x), lo = rn(x - hi))
__device__ __forceinline__ void split_bf16(float x, __nv_bfloat16& hi, __nv_bfloat16& lo) {
    hi = __float2bfloat16(x);
    lo = __float2bfloat16(x - __bfloat162float(hi));
}

// ================= relation bucketing (counting sort) ===========
__global__ void bucket_zero_kernel() {
    int i = threadIdx.x;
    if (i < NR) g_rel_cnt[i] = 0;
}

__global__ __launch_bounds__(256) void hist_kernel(const int* __restrict__ et) {
    __shared__ int sh[NR];
    for (int i = threadIdx.x; i < NR; i += 256) sh[i] = 0;
    __syncthreads();
    int e = blockIdx.x * 1024 + threadIdx.x;
#pragma unroll
    for (int i = 0; i < 4; i++) atomicAdd(&sh[et[e + i * 256]], 1);
    __syncthreads();
    for (int i = threadIdx.x; i < NR; i += 256)
        if (sh[i]) atomicAdd(&g_rel_cnt[i], sh[i]);
}

__global__ void scan_kernel() {
    if (threadIdx.x == 0) {
        int acc = 0;
        for (int i = 0; i < NR; i++) {
            g_rel_cur[i] = acc;
            acc += g_rel_cnt[i];
        }
    }
}

__global__ __launch_bounds__(256) void scatter_kernel(const int* __restrict__ et) {
    __shared__ int loc_cnt[NR];
    __shared__ int loc_base[NR];
    int t = threadIdx.x;
    for (int i = t; i < NR; i += 256) loc_cnt[i] = 0;
    __syncthreads();
    int e0 = blockIdx.x * 1024 + t;
    int r[4], idx[4];
#pragma unroll
    for (int i = 0; i < 4; i++) {
        r[i] = et[e0 + i * 256];
        idx[i] = atomicAdd(&loc_cnt[r[i]], 1);
    }
    __syncthreads();
    for (int i = t; i < NR; i += 256)
        loc_base[i] = loc_cnt[i] ? atomicAdd(&g_rel_cur[i], loc_cnt[i]) : 0;
    __syncthreads();
#pragma unroll
    for (int i = 0; i < 4; i++)
        g_perm[loc_base[r[i]] + idx[i]] = e0 + i * 256;
}

// ================= self-loop layer 1: out1 = X@lw1 + b1 =========
__global__ void selfloop1_kernel(const float* __restrict__ embed,
                                 const int* __restrict__ h,
                                 const float* __restrict__ lw1,
                                 const float* __restrict__ b1) {
    __shared__ float xs[8][HD];
    int t = threadIdx.x;
    int n0 = blockIdx.x * 8;
#pragma unroll
    for (int nb = 0; nb < 8; nb++) {
        int node = n0 + nb;
        xs[nb][t] = embed[(size_t)h[node] * HD + t];
    }
    __syncthreads();
    float acc[8] = {0,0,0,0,0,0,0,0};
#pragma unroll 4
    for (int k = 0; k < HD; k++) {
        float w = lw1[k * HD + t];
#pragma unroll
        for (int nb = 0; nb < 8; nb++) acc[nb] = fmaf(xs[nb][k], w, acc[nb]);
    }
    float bias = b1[t];
#pragma unroll
    for (int nb = 0; nb < 8; nb++)
        g_out1[(size_t)(n0 + nb) * HD + t] = acc[nb] + bias;
}

// ====== edge layer 1, relation-sorted: 8 edges per warp =========
__global__ __launch_bounds__(256) void edge1_kernel(
        const float* __restrict__ embed,
        const int* __restrict__ h,
        const int* __restrict__ src,
        const int* __restrict__ dst,
        const int* __restrict__ et,
        const float* __restrict__ norm,
        const float* __restrict__ W1) {
    int w = blockIdx.x * 8 + (threadIdx.x >> 5);
    int l = threadIdx.x & 31;
    int e0 = w * 8;
    int pe[8];
#pragma unroll
    for (int i = 0; i < 8; i++) pe[i] = g_perm[e0 + i];
    int r0 = et[pe[0]];
    bool uni = (r0 == et[pe[7]]);   // sorted by rel: first==last -> all equal
    float4 w0 = make_float4(0, 0, 0, 0), w1 = w0;
    if (uni) {
        const float* wp = W1 + (size_t)r0 * 256 + l * 8;  // [64][2][2] per rel
        w0 = *(const float4*)(wp);
        w1 = *(const float4*)(wp + 4);
    }
    int s[8], d[8];
    float nr[8];
#pragma unroll
    for (int i = 0; i < 8; i++) {
        s[i] = src[pe[i]]; d[i] = dst[pe[i]]; nr[i] = norm[pe[i]];
    }
    int hs[8];
#pragma unroll
    for (int i = 0; i < 8; i++) hs[i] = h[s[i]];
#pragma unroll
    for (int i = 0; i < 8; i++) {
        float4 xv = *(const float4*)(embed + (size_t)hs[i] * HD + 4 * l);
        float4 v0 = w0, v1 = w1;
        if (!uni) {
            const float* wp = W1 + (size_t)et[pe[i]] * 256 + l * 8;
            v0 = *(const float4*)(wp);
            v1 = *(const float4*)(wp + 4);
        }
        float m0 = (xv.x * v0.x + xv.y * v0.z) * nr[i];
        float m1 = (xv.x * v0.y + xv.y * v0.w) * nr[i];
        float m2 = (xv.z * v1.x + xv.w * v1.z) * nr[i];
        float m3 = (xv.z * v1.y + xv.w * v1.w) * nr[i];
        red_add_v4(g_out1 + (size_t)d[i] * HD + 4 * l, m0, m1, m2, m3);
    }
}

// ================= self-loop layer 2: out2 = relu(out1)@lw2 + b2
__global__ void selfloop2_kernel(const float* __restrict__ lw2,
                                 const float* __restrict__ b2) {
    __shared__ float xs[4][HD];
    int t = threadIdx.x;
    int n0 = blockIdx.x * 4;
    for (int idx = t; idx < 4 * HD; idx += 256) {
        int nb = idx >> 7, k = idx & 127;
        float v = g_out1[(size_t)(n0 + nb) * HD + k];
        xs[nb][k] = v > 0.f ? v : 0.f;
    }
    __syncthreads();
    float acc[4] = {0,0,0,0};
#pragma unroll 4
    for (int k = 0; k < HD; k++) {
        float w = lw2[k * 256 + t];
#pragma unroll
        for (int nb = 0; nb < 4; nb++) acc[nb] = fmaf(xs[nb][k], w, acc[nb]);
    }
    float bias = b2[t];
#pragma unroll
    for (int nb = 0; nb < 4; nb++)
        g_out2[(size_t)(n0 + nb) * 256 + t] = acc[nb] + bias;
}

// ====== edge layer 2, relation-sorted: 8 edges per warp =========
__global__ __launch_bounds__(256) void edge2_kernel(
        const int* __restrict__ src,
        const int* __restrict__ dst,
        const int* __restrict__ et,
        const float* __restrict__ norm,
        const float* __restrict__ W2) {
    int w = blockIdx.x * 8 + (threadIdx.x >> 5);
    int l = threadIdx.x & 31;
    int e0 = w * 8;
    int pe[8];
#pragma unroll
    for (int i = 0; i < 8; i++) pe[i] = g_perm[e0 + i];
    int r0 = et[pe[0]];
    bool uni = (r0 == et[pe[7]]);
    float4 wa0, wa1, wb0, wb1;
    if (uni) {
        const float* wp = W2 + (size_t)r0 * 512 + l * 16;  // [64][2][4] per rel
        wa0 = *(const float4*)(wp);
        wa1 = *(const float4*)(wp + 4);
        wb0 = *(const float4*)(wp + 8);
        wb1 = *(const float4*)(wp + 12);
    } else {
        wa0 = wa1 = wb0 = wb1 = make_float4(0, 0, 0, 0);
    }
    int s[8], d[8];
    float nr[8];
#pragma unroll
    for (int i = 0; i < 8; i++) {
        s[i] = src[pe[i]]; d[i] = dst[pe[i]]; nr[i] = norm[pe[i]];
    }
#pragma unroll
    for (int i = 0; i < 8; i++) {
        float4 xv = *(const float4*)(g_out1 + (size_t)s[i] * HD + 4 * l);
        xv.x = xv.x > 0.f ? xv.x : 0.f;
        xv.y = xv.y > 0.f ? xv.y : 0.f;
        xv.z = xv.z > 0.f ? xv.z : 0.f;
        xv.w = xv.w > 0.f ? xv.w : 0.f;
        float4 va0 = wa0, va1 = wa1, vb0 = wb0, vb1 = wb1;
        if (!uni) {
            const float* wp = W2 + (size_t)et[pe[i]] * 512 + l * 16;
            va0 = *(const float4*)(wp);
            va1 = *(const float4*)(wp + 4);
            vb0 = *(const float4*)(wp + 8);
            vb1 = *(const float4*)(wp + 12);
        }
        float m0 = (xv.x * va0.x + xv.y * va1.x) * nr[i];
        float m1 = (xv.x * va0.y + xv.y * va1.y) * nr[i];
        float m2 = (xv.x * va0.z + xv.y * va1.z) * nr[i];
        float m3 = (xv.x * va0.w + xv.y * va1.w) * nr[i];
        float m4 = (xv.z * vb0.x + xv.w * vb1.x) * nr[i];
        float m5 = (xv.z * vb0.y + xv.w * vb1.y) * nr[i];
        float m6 = (xv.z * vb0.z + xv.w * vb1.z) * nr[i];
        float m7 = (xv.z * vb0.w + xv.w * vb1.w) * nr[i];
        float* p = g_out2 + (size_t)d[i] * 256 + 8 * l;
        red_add_v4(p,     m0, m1, m2, m3);
        red_add_v4(p + 4, m4, m5, m6, m7);
    }
}

// ====== z = m + sqrt(softplus(hv)+1e-8)*eps; also split to bf16 ==
__global__ void z_kernel(const float* __restrict__ eps) {
    int i = blockIdx.x * blockDim.x + threadIdx.x;   // over N*HD
    if (i >= NNODES * HD) return;
    int n = i >> 7, j = i & 127;
    float m  = g_out2[(size_t)n * 256 + j];
    float hv = g_out2[(size_t)n * 256 + 128 + j];
    float sp = fmaxf(hv, 0.f) + log1pf(expf(-fabsf(hv)));
    float v = sp + 1e-8f;
    float z = fmaf(sqrtf(v), eps[i], m);
    g_z[i] = z;
    __nv_bfloat16 hi, lo;
    split_bf16(z, hi, lo);
    g_z_hi[i] = hi;
    g_z_lo[i] = lo;
}

// ====== hr = z[head] * w_rel[rel], split to bf16 ================
__global__ void hr_kernel(const int* __restrict__ head_ids,
                          const int* __restrict__ rel_ids,
                          const float* __restrict__ w_rel) {
    int i = blockIdx.x * blockDim.x + threadIdx.x;   // over NQ*HD
    if (i >= NQ * HD) return;
    int b = i >> 7, j = i & 127;
    float hr = g_z[(size_t)head_ids[b] * HD + j] * w_rel[(size_t)rel_ids[b] * HD + j];
    __nv_bfloat16 hi, lo;
    split_bf16(hr, hi, lo);
    g_hr_hi[i] = hi;
    g_hr_lo[i] = lo;
}

// ================= scores = hr @ z^T via mma.sync (bf16 split) ==
// Tile 128x128 per CTA, 8 warps (2x4), warp tile 64x32, K=128 resident.
// smem rows padded to 136 bf16 (272B): ldmatrix conflict-free.
#define TM 128
#define TN 128
#define PAD_K   136
#define TILE_B  (128 * PAD_K * 2)          // 34816 bytes per buffer
#define S2_A_HI 0
#define S2_A_LO (S2_A_HI + TILE_B)
#define S2_B_HI (S2_A_LO + TILE_B)
#define S2_B_LO (S2_B_HI + TILE_B)
#define S2_TOTAL (4 * TILE_B)              // 139264 bytes

__global__ __launch_bounds__(256, 1) void scores_mma_kernel(float* __restrict__ C) {
    extern __shared__ char smem[];
    uint32_t sb = smem_to_u32(smem);
    int tid = threadIdx.x;
    int wid = tid >> 5, lid = tid & 31;
    int m0 = blockIdx.y * TM;
    int n0 = blockIdx.x * TN;

    // ---- stage tiles gmem(bf16) -> smem (padded rows) ----
    for (int u = tid; u < 2048; u += 256) {
        int row = u >> 4, ch = u & 15;
        uint32_t so = (uint32_t)row * (PAD_K * 2) + ch * 16;
        size_t ga = (size_t)(m0 + row) * HD + ch * 8;
        *(uint4*)(smem + S2_A_HI + so) = *(const uint4*)(g_hr_hi + ga);
        *(uint4*)(smem + S2_A_LO + so) = *(const uint4*)(g_hr_lo + ga);
        int gn = n0 + row;
        uint4 bh = make_uint4(0, 0, 0, 0), bl = make_uint4(0, 0, 0, 0);
        if (gn < NNODES) {
            size_t gb = (size_t)gn * HD + ch * 8;
            bh = *(const uint4*)(g_z_hi + gb);
            bl = *(const uint4*)(g_z_lo + gb);
        }
        *(uint4*)(smem + S2_B_HI + so) = bh;
        *(uint4*)(smem + S2_B_LO + so) = bl;
    }
    __syncthreads();

    int wm = (wid & 1) * 64;        // warp m offset within tile
    int wn = (wid >> 1) * 32;       // warp n offset within tile
    int r8 = lid & 7, g = lid >> 3;

    uint32_t a_off = (uint32_t)((g & 1) * 8 + r8) * (PAD_K * 2) + (uint32_t)(g >> 1) * 16;
    uint32_t b_off = (uint32_t)((g >> 1) * 8 + r8) * (PAD_K * 2) + (uint32_t)(g & 1) * 16;

    float acc[4][4][4];
#pragma unroll
    for (int i = 0; i < 4; i++)
#pragma unroll
        for (int j = 0; j < 4; j++)
#pragma unroll
            for (int q = 0; q < 4; q++) acc[i][j][q] = 0.f;

    const uint32_t aBase[3] = { sb + S2_A_HI, sb + S2_A_HI, sb + S2_A_LO };
    const uint32_t bBase[3] = { sb + S2_B_HI, sb + S2_B_LO, sb + S2_B_HI };

#pragma unroll
    for (int pass = 0; pass < 3; pass++) {
        uint32_t aB = aBase[pass] + (uint32_t)wm * (PAD_K * 2) + a_off;
        uint32_t bB = bBase[pass] + (uint32_t)wn * (PAD_K * 2) + b_off;
#pragma unroll
        for (int kk = 0; kk < 8; kk++) {
            uint32_t af[4][4], bf[2][4];
#pragma unroll
            for (int mi = 0; mi < 4; mi++)
                ldsm_x4(aB + (uint32_t)mi * 16 * (PAD_K * 2) + kk * 32, af[mi]);
#pragma unroll
            for (int nj = 0; nj < 2; nj++)
                ldsm_x4(bB + (uint32_t)nj * 16 * (PAD_K * 2) + kk * 32, bf[nj]);
#pragma unroll
            for (int mi = 0; mi < 4; mi++) {
#pragma unroll
                for (int nf = 0; nf < 4; nf++)
                    mma_bf16(acc[mi][nf], af[mi], &bf[nf >> 1][(nf & 1) * 2]);
            }
        }
    }

    // ---- epilogue: direct stores ----
    int mrow = lid >> 2;            // 0..7
    int ncol = (lid & 3) * 2;       // 0,2,4,6
#pragma unroll
    for (int mi = 0; mi < 4; mi++) {
#pragma unroll
        for (int nf = 0; nf < 4; nf++) {
            int gm = m0 + wm + mi * 16 + mrow;
            int gn = n0 + wn + nf * 8 + ncol;
            if (gn < NNODES) {
                *(float2*)(C + (size_t)gm * NNODES + gn) =
                    make_float2(acc[mi][nf][0], acc[mi][nf][1]);
                *(float2*)(C + (size_t)(gm + 8) * NNODES + gn) =
                    make_float2(acc[mi][nf][2], acc[mi][nf][3]);
            }
        }
    }
}

// =================================================================
extern "C" void kernel_launch(void* const* d_in, const int* in_sizes, int n_in,
                              void* d_out, int out_size) {
    const int*   h        = (const int*)d_in[0];
    const int*   src      = (const int*)d_in[1];
    const int*   dst      = (const int*)d_in[2];
    const int*   etypes   = (const int*)d_in[3];
    const float* norm     = (const float*)d_in[4];
    const int*   head_ids = (const int*)d_in[5];
    const int*   rel_ids  = (const int*)d_in[6];
    const float* embed    = (const float*)d_in[7];
    const float* W1       = (const float*)d_in[8];
    const float* lw1      = (const float*)d_in[9];
    const float* b1       = (const float*)d_in[10];
    const float* W2       = (const float*)d_in[11];
    const float* lw2      = (const float*)d_in[12];
    const float* b2       = (const float*)d_in[13];
    const float* w_rel    = (const float*)d_in[14];
    const float* eps      = (const float*)d_in[15];
    float* out = (float*)d_out;

    cudaFuncSetAttribute(scores_mma_kernel,
                         cudaFuncAttributeMaxDynamicSharedMemorySize, S2_TOTAL);

    // ---- relation bucketing (shared by both edge layers) ----
    bucket_zero_kernel<<<1, 128>>>();
    hist_kernel<<<NEDGES / 1024, 256>>>(etypes);
    scan_kernel<<<1, 32>>>();
    scatter_kernel<<<NEDGES / 1024, 256>>>(etypes);

    selfloop1_kernel<<<NNODES / 8, 128>>>(embed, h, lw1, b1);
    edge1_kernel<<<NEDGES / 64, 256>>>(embed, h, src, dst, etypes, norm, W1);

    selfloop2_kernel<<<NNODES / 4, 256>>>(lw2, b2);
    edge2_kernel<<<NEDGES / 64, 256>>>(src, dst, etypes, norm, W2);

    z_kernel<<<(NNODES * HD + 255) / 256, 256>>>(eps);

    hr_kernel<<<(NQ * HD + 255) / 256, 256>>>(head_ids, rel_ids, w_rel);

    dim3 grid((NNODES + TN - 1) / TN, NQ / TM);
    scores_mma_kernel<<<grid, 256, S2_TOTAL>>>(out);
}